// round 3
// baseline (speedup 1.0000x reference)
#include <cuda_runtime.h>

#define NROWS_MAX 65536
typedef unsigned long long ull;

// 16 MB scratch: [n][0..31]=left, [n][32..63]=right
__device__ __align__(16) float g_lr[(size_t)NROWS_MAX * 64];

// ---------- packed f32x2 helpers ----------
__device__ __forceinline__ ull pk2(float x) {
    ull r; asm("mov.b64 %0, {%1, %1};" : "=l"(r) : "f"(x)); return r;
}
__device__ __forceinline__ void fma2(ull &d, ull a, ull b) {
    asm("fma.rn.f32x2 %0, %1, %2, %0;" : "+l"(d) : "l"(a), "l"(b));
}
__device__ __forceinline__ ull mul2(ull a, ull b) {
    ull d; asm("mul.rn.f32x2 %0, %1, %2;" : "=l"(d) : "l"(a), "l"(b)); return d;
}
__device__ __forceinline__ float2 up2(ull v) {
    float2 f; asm("mov.b64 {%0, %1}, %2;" : "=f"(f.x), "=f"(f.y) : "l"(v)); return f;
}

// =====================================================================
// Kernel A: left = im(na, b) @ Wa + ba ; right = im(c, d) @ Wa + ba
// Grid: 2*(N/128) blocks x 128 threads. BM=128, BN=32, K=1088 factored.
// =====================================================================
#define PADA 132
__global__ __launch_bounds__(128, 4) void k_lr(
    const float* __restrict__ concepts, const float* __restrict__ Wn,
    const float* __restrict__ bn, const float* __restrict__ Wa,
    const float* __restrict__ ba, const void* __restrict__ idxp,
    int nrows)
{
    __shared__ __align__(16) float uT[32 * PADA];   // uT[i][r]
    __shared__ __align__(16) float vT[32 * PADA];   // vT[j][r]
    __shared__ __align__(16) float Bs[32 * 32];

    int tid  = threadIdx.x;
    int lane = tid & 31, w = tid >> 5;
    int nb128 = nrows >> 7;
    bool leftside = (blockIdx.x < (unsigned)nb128);
    int n0 = (leftside ? blockIdx.x : blockIdx.x - nb128) << 7;
    int cu_col = leftside ? 0 : 2;

    // runtime int64-vs-int32 idx detection (int64 high words are all 0)
    const int* idx32 = (const int*)idxp;
    bool is64 = (idx32[1] == 0) & (idx32[3] == 0) & (idx32[5] == 0) & (idx32[7] == 0);
    const long long* idx64 = (const long long*)idxp;

    for (int it = 0; it < 32; ++it) {
        int r = it * 4 + w;
        long long base = (long long)(n0 + r) * 4 + cu_col;
        long long cu = is64 ? idx64[base]     : (long long)idx32[base];
        long long cv = is64 ? idx64[base + 1] : (long long)idx32[base + 1];
        uT[lane * PADA + r] = concepts[cu * 32 + lane];
        vT[lane * PADA + r] = concepts[cv * 32 + lane];
    }
    __syncthreads();

    if (leftside) {
        // na = a @ Wn + bn, in place over uT
        for (int e = tid; e < 1024; e += 128) Bs[e] = Wn[e];
        __syncthreads();
        float bnk = bn[lane];
        for (int rr = 0; rr < 32; ++rr) {
            int r = (w << 5) + rr;                 // warp w owns rows [32w, 32w+32)
            float na = bnk;
            #pragma unroll
            for (int i2 = 0; i2 < 32; ++i2)
                na = fmaf(uT[i2 * PADA + r], Bs[i2 * 32 + lane], na);
            __syncwarp();
            uT[lane * PADA + r] = na;
            __syncwarp();
        }
    }
    __syncthreads();

    // register-tiled GEMM: 128x32, per-thread 8 rows x 4 cols (2 f32x2)
    int tc = tid & 7, tr = tid >> 3;
    int c0 = tc << 2, r0 = tr << 3;
    ull acc[8][2];
    #pragma unroll
    for (int m = 0; m < 8; ++m) { acc[m][0] = 0ull; acc[m][1] = 0ull; }

    for (int s = 0; s < 34; ++s) {
        #pragma unroll
        for (int q = 0; q < 2; ++q) {
            int e4 = (tid << 1) + q;
            int k = e4 >> 3, c4 = e4 & 7;
            *(float4*)&Bs[(k << 5) + (c4 << 2)] =
                *(const float4*)&Wa[(s * 32 + k) * 32 + (c4 << 2)];
        }
        __syncthreads();

        if (s >= 2) {
            int ii = s - 2;
            ull qa[8][2];
            {   // kk = 0 initializes q = v_j * Wa[64+32*ii+j, c]
                float4 va = *(const float4*)&vT[r0];
                float4 vb = *(const float4*)&vT[r0 + 4];
                ulonglong2 Bv = *(const ulonglong2*)&Bs[c0];
                float vv[8] = {va.x, va.y, va.z, va.w, vb.x, vb.y, vb.z, vb.w};
                #pragma unroll
                for (int m = 0; m < 8; ++m) {
                    ull pp = pk2(vv[m]);
                    qa[m][0] = mul2(pp, Bv.x);
                    qa[m][1] = mul2(pp, Bv.y);
                }
            }
            #pragma unroll
            for (int kk = 1; kk < 32; ++kk) {
                float4 va = *(const float4*)&vT[kk * PADA + r0];
                float4 vb = *(const float4*)&vT[kk * PADA + r0 + 4];
                ulonglong2 Bv = *(const ulonglong2*)&Bs[(kk << 5) + c0];
                float vv[8] = {va.x, va.y, va.z, va.w, vb.x, vb.y, vb.z, vb.w};
                #pragma unroll
                for (int m = 0; m < 8; ++m) {
                    ull pp = pk2(vv[m]);
                    fma2(qa[m][0], pp, Bv.x);
                    fma2(qa[m][1], pp, Bv.y);
                }
            }
            #pragma unroll
            for (int m = 0; m < 8; ++m) {
                ull uu = pk2(uT[ii * PADA + r0 + m]);
                fma2(acc[m][0], uu, qa[m][0]);
                fma2(acc[m][1], uu, qa[m][1]);
            }
        } else {
            const float* S = (s == 0) ? uT : vT;   // linear u- then v-features
            #pragma unroll
            for (int kk = 0; kk < 32; ++kk) {
                float4 va = *(const float4*)&S[kk * PADA + r0];
                float4 vb = *(const float4*)&S[kk * PADA + r0 + 4];
                ulonglong2 Bv = *(const ulonglong2*)&Bs[(kk << 5) + c0];
                float vv[8] = {va.x, va.y, va.z, va.w, vb.x, vb.y, vb.z, vb.w};
                #pragma unroll
                for (int m = 0; m < 8; ++m) {
                    ull pp = pk2(vv[m]);
                    fma2(acc[m][0], pp, Bv.x);
                    fma2(acc[m][1], pp, Bv.y);
                }
            }
        }
        __syncthreads();
    }

    float4 bav = *(const float4*)&ba[c0];
    int hoff = leftside ? 0 : 32;
    #pragma unroll
    for (int m = 0; m < 8; ++m) {
        float2 p0 = up2(acc[m][0]);
        float2 p1 = up2(acc[m][1]);
        float4 o;
        o.x = p0.x + bav.x; o.y = p0.y + bav.y;
        o.z = p1.x + bav.z; o.w = p1.y + bav.w;
        *(float4*)&g_lr[(size_t)(n0 + r0 + m) * 64 + hoff + c0] = o;
    }
}

// =====================================================================
// Kernel B: s = im(left,right) @ Ws1 + bs1; out = elu(s) @ Ws2 + bs2
// Grid: N/64 blocks x 256 threads. BM=64, BN=128, K=1088 factored.
// =====================================================================
#define PADL 33
#define PADR 132
__global__ __launch_bounds__(256, 2) void k_main(
    const float* __restrict__ Ws1, const float* __restrict__ bs1,
    const float* __restrict__ Ws2, const float* __restrict__ bs2,
    float* __restrict__ out)
{
    __shared__ __align__(16) float Lp[64 * PADL];     // Lp[r][i]  (left)
    __shared__ __align__(16) float RT2[32 * PADR];    // RT2[j][2r..2r+1] = (R,R)
    __shared__ __align__(16) float Bs[32 * 128];

    int tid = threadIdx.x;
    int n0 = blockIdx.x << 6;

    #pragma unroll
    for (int it = 0; it < 16; ++it) {
        int e = it * 256 + tid;
        int r = e >> 6, k = e & 63;
        float v = g_lr[(size_t)(n0 + r) * 64 + k];
        if (k < 32) Lp[r * PADL + k] = v;
        else        *(ull*)&RT2[(k - 32) * PADR + (r << 1)] = pk2(v);
    }
    __syncthreads();

    int tc = tid & 31, w = tid >> 5;
    int c0 = tc << 2, r0 = w << 3;
    ull acc[8][2];
    #pragma unroll
    for (int m = 0; m < 8; ++m) { acc[m][0] = 0ull; acc[m][1] = 0ull; }

    for (int s = 0; s < 34; ++s) {
        #pragma unroll
        for (int q = 0; q < 4; ++q) {
            int e4 = q * 256 + tid;
            int k = e4 >> 5, c4 = e4 & 31;
            *(float4*)&Bs[(k << 7) + (c4 << 2)] =
                *(const float4*)&Ws1[(size_t)(s * 32 + k) * 128 + (c4 << 2)];
        }
        __syncthreads();

        if (s >= 2) {
            int ii = s - 2;
            ull qa[8][2];
            {   // kk = 0
                ulonglong2 Bv = *(const ulonglong2*)&Bs[c0];
                #pragma unroll
                for (int m = 0; m < 8; ++m) {
                    ull rv = *(const ull*)&RT2[(r0 + m) << 1];
                    qa[m][0] = mul2(rv, Bv.x);
                    qa[m][1] = mul2(rv, Bv.y);
                }
            }
            #pragma unroll
            for (int kk = 1; kk < 32; ++kk) {
                ulonglong2 Bv = *(const ulonglong2*)&Bs[(kk << 7) + c0];
                #pragma unroll
                for (int m = 0; m < 8; ++m) {
                    ull rv = *(const ull*)&RT2[kk * PADR + ((r0 + m) << 1)];
                    fma2(qa[m][0], rv, Bv.x);
                    fma2(qa[m][1], rv, Bv.y);
                }
            }
            #pragma unroll
            for (int m = 0; m < 8; ++m) {
                ull uu = pk2(Lp[(r0 + m) * PADL + ii]);
                fma2(acc[m][0], uu, qa[m][0]);
                fma2(acc[m][1], uu, qa[m][1]);
            }
        } else if (s == 0) {        // linear-left features
            #pragma unroll
            for (int kk = 0; kk < 32; ++kk) {
                ulonglong2 Bv = *(const ulonglong2*)&Bs[(kk << 7) + c0];
                #pragma unroll
                for (int m = 0; m < 8; ++m) {
                    ull pp = pk2(Lp[(r0 + m) * PADL + kk]);
                    fma2(acc[m][0], pp, Bv.x);
                    fma2(acc[m][1], pp, Bv.y);
                }
            }
        } else {                    // s == 1: linear-right features
            #pragma unroll
            for (int kk = 0; kk < 32; ++kk) {
                ulonglong2 Bv = *(const ulonglong2*)&Bs[(kk << 7) + c0];
                #pragma unroll
                for (int m = 0; m < 8; ++m) {
                    ull rv = *(const ull*)&RT2[kk * PADR + ((r0 + m) << 1)];
                    fma2(acc[m][0], rv, Bv.x);
                    fma2(acc[m][1], rv, Bv.y);
                }
            }
        }
        __syncthreads();
    }

    // epilogue: +bs1, elu, dot with Ws2, warp-reduce over 128 cols
    float4 b1 = *(const float4*)&bs1[c0];
    float4 w2 = *(const float4*)&Ws2[c0];
    float bias2 = bs2[0];
    #pragma unroll
    for (int m = 0; m < 8; ++m) {
        float2 p0 = up2(acc[m][0]);
        float2 p1 = up2(acc[m][1]);
        float x0 = p0.x + b1.x, x1 = p0.y + b1.y;
        float x2 = p1.x + b1.z, x3 = p1.y + b1.w;
        float h0 = x0 > 0.f ? x0 : expm1f(x0);
        float h1 = x1 > 0.f ? x1 : expm1f(x1);
        float h2 = x2 > 0.f ? x2 : expm1f(x2);
        float h3 = x3 > 0.f ? x3 : expm1f(x3);
        float p = fmaf(h0, w2.x, fmaf(h1, w2.y, fmaf(h2, w2.z, h3 * w2.w)));
        #pragma unroll
        for (int off = 16; off; off >>= 1)
            p += __shfl_xor_sync(0xffffffffu, p, off);
        if (tc == 0) out[n0 + r0 + m] = p + bias2;
    }
}

extern "C" void kernel_launch(void* const* d_in, const int* in_sizes, int n_in,
                              void* d_out, int out_size)
{
    const float* concepts = (const float*)d_in[0];
    const float* Wn  = (const float*)d_in[1];
    const float* bn  = (const float*)d_in[2];
    const float* Wa  = (const float*)d_in[3];
    const float* ba  = (const float*)d_in[4];
    const float* Ws1 = (const float*)d_in[5];
    const float* bs1 = (const float*)d_in[6];
    const float* Ws2 = (const float*)d_in[7];
    const float* bs2 = (const float*)d_in[8];
    const void*  idx = d_in[9];
    int nrows = in_sizes[9] / 4;   // idx element count is N*4 for either dtype

    k_lr<<<(nrows / 128) * 2, 128>>>(concepts, Wn, bn, Wa, ba, idx, nrows);
    k_main<<<nrows / 64, 256>>>(Ws1, bs1, Ws2, bs2, (float*)d_out);
}

// round 4
// speedup vs baseline: 1.0435x; 1.0435x over previous
#include <cuda_runtime.h>
#include <cstdint>

#define NROWS_MAX 65536
typedef unsigned long long ull;

// 16 MB scratch: [n][0..31]=left, [n][32..63]=right
__device__ __align__(16) float g_lr[(size_t)NROWS_MAX * 64];

// ---------- packed f32x2 helpers ----------
__device__ __forceinline__ ull pk2(float x) {
    ull r; asm("mov.b64 %0, {%1, %1};" : "=l"(r) : "f"(x)); return r;
}
__device__ __forceinline__ void fma2(ull &d, ull a, ull b) {
    asm("fma.rn.f32x2 %0, %1, %2, %0;" : "+l"(d) : "l"(a), "l"(b));
}
__device__ __forceinline__ ull mul2(ull a, ull b) {
    ull d; asm("mul.rn.f32x2 %0, %1, %2;" : "=l"(d) : "l"(a), "l"(b)); return d;
}
__device__ __forceinline__ float2 up2(ull v) {
    float2 f; asm("mov.b64 {%0, %1}, %2;" : "=f"(f.x), "=f"(f.y) : "l"(v)); return f;
}
// ---------- cp.async helpers ----------
__device__ __forceinline__ uint32_t s2u(const void* p) {
    uint32_t a;
    asm("{ .reg .u64 t; cvta.to.shared.u64 t, %1; cvt.u32.u64 %0, t; }" : "=r"(a) : "l"(p));
    return a;
}
__device__ __forceinline__ void cpa16(uint32_t dst, const float* src) {
    asm volatile("cp.async.ca.shared.global [%0], [%1], 16;" :: "r"(dst), "l"(src));
}
__device__ __forceinline__ void cpa_commit() {
    asm volatile("cp.async.commit_group;");
}
template<int N> __device__ __forceinline__ void cpa_wait() {
    asm volatile("cp.async.wait_group %0;" :: "n"(N));
}

// =====================================================================
// Kernel A: left = im(na, b) @ Wa + ba ; right = im(c, d) @ Wa + ba
// Grid: 2*(N/128) blocks x 128 threads. BM=128, BN=32, K=1088 factored.
// 3-stage cp.async pipeline on the Wa K-chunks.
// =====================================================================
#define PADA 132
__global__ __launch_bounds__(128, 4) void k_lr(
    const float* __restrict__ concepts, const float* __restrict__ Wn,
    const float* __restrict__ bn, const float* __restrict__ Wa,
    const float* __restrict__ ba, const void* __restrict__ idxp,
    int nrows)
{
    __shared__ __align__(16) float uT[32 * PADA];   // uT[i][r]
    __shared__ __align__(16) float vT[32 * PADA];   // vT[j][r]
    __shared__ __align__(16) float Bs[3 * 1024];    // 3-stage ring of Wa chunks

    int tid  = threadIdx.x;
    int lane = tid & 31, w = tid >> 5;
    int nb128 = nrows >> 7;
    bool leftside = (blockIdx.x < (unsigned)nb128);
    int n0 = (leftside ? blockIdx.x : blockIdx.x - nb128) << 7;
    int cu_col = leftside ? 0 : 2;

    uint32_t bs_base = s2u(Bs);
    // per-thread cp.async lane: 2 x 16B per chunk, chunk is a flat 4KB copy
    int e0 = tid * 2;                 // float4 index 0
    // prefetch chunks 0,1
    #pragma unroll
    for (int p = 0; p < 2; ++p) {
        #pragma unroll
        for (int q = 0; q < 2; ++q)
            cpa16(bs_base + ((p % 3) * 1024 + (e0 + q) * 4) * 4,
                  Wa + (size_t)p * 1024 + (e0 + q) * 4);
        cpa_commit();
    }

    // runtime int64-vs-int32 idx detection (int64 high words are all 0)
    const int* idx32 = (const int*)idxp;
    bool is64 = (idx32[1] == 0) & (idx32[3] == 0) & (idx32[5] == 0) & (idx32[7] == 0);
    const long long* idx64 = (const long long*)idxp;

    for (int it = 0; it < 32; ++it) {
        int r = it * 4 + w;
        long long base = (long long)(n0 + r) * 4 + cu_col;
        long long cu = is64 ? idx64[base]     : (long long)idx32[base];
        long long cv = is64 ? idx64[base + 1] : (long long)idx32[base + 1];
        uT[lane * PADA + r] = concepts[cu * 32 + lane];
        vT[lane * PADA + r] = concepts[cv * 32 + lane];
    }
    __syncthreads();

    if (leftside) {
        // na = a @ Wn + bn, in place over uT; Wn cached in registers
        float wn[32];
        #pragma unroll
        for (int i2 = 0; i2 < 32; ++i2) wn[i2] = Wn[i2 * 32 + lane];
        float bnk = bn[lane];
        for (int rr = 0; rr < 32; ++rr) {
            int r = (w << 5) + rr;                 // warp w owns rows [32w, 32w+32)
            float na = bnk;
            #pragma unroll
            for (int i2 = 0; i2 < 32; ++i2)
                na = fmaf(uT[i2 * PADA + r], wn[i2], na);
            __syncwarp();
            uT[lane * PADA + r] = na;
            __syncwarp();
        }
    }
    __syncthreads();

    // register-tiled GEMM: 128x32, per-thread 8 rows x 4 cols (2 f32x2)
    int tc = tid & 7, tr = tid >> 3;
    int c0 = tc << 2, r0 = tr << 3;
    ull acc[8][2];
    #pragma unroll
    for (int m = 0; m < 8; ++m) { acc[m][0] = 0ull; acc[m][1] = 0ull; }

    for (int s = 0; s < 34; ++s) {
        cpa_wait<1>();          // chunk s landed (s+1 may be in flight)
        __syncthreads();        // visibility of all threads' copies; frees buf (s+2)%3
        if (s + 2 < 34) {
            #pragma unroll
            for (int q = 0; q < 2; ++q)
                cpa16(bs_base + (((s + 2) % 3) * 1024 + (e0 + q) * 4) * 4,
                      Wa + (size_t)(s + 2) * 1024 + (e0 + q) * 4);
        }
        cpa_commit();

        const float* Bc = Bs + (s % 3) * 1024;

        if (s >= 2) {
            int ii = s - 2;
            ull qa[8][2];
            {   // kk = 0 initializes q = v_j * Wa[64+32*ii+j, c]
                float4 va = *(const float4*)&vT[r0];
                float4 vb = *(const float4*)&vT[r0 + 4];
                ulonglong2 Bv = *(const ulonglong2*)&Bc[c0];
                float vv[8] = {va.x, va.y, va.z, va.w, vb.x, vb.y, vb.z, vb.w};
                #pragma unroll
                for (int m = 0; m < 8; ++m) {
                    ull pp = pk2(vv[m]);
                    qa[m][0] = mul2(pp, Bv.x);
                    qa[m][1] = mul2(pp, Bv.y);
                }
            }
            #pragma unroll
            for (int kk = 1; kk < 32; ++kk) {
                float4 va = *(const float4*)&vT[kk * PADA + r0];
                float4 vb = *(const float4*)&vT[kk * PADA + r0 + 4];
                ulonglong2 Bv = *(const ulonglong2*)&Bc[(kk << 5) + c0];
                float vv[8] = {va.x, va.y, va.z, va.w, vb.x, vb.y, vb.z, vb.w};
                #pragma unroll
                for (int m = 0; m < 8; ++m) {
                    ull pp = pk2(vv[m]);
                    fma2(qa[m][0], pp, Bv.x);
                    fma2(qa[m][1], pp, Bv.y);
                }
            }
            #pragma unroll
            for (int m = 0; m < 8; ++m) {
                ull uu = pk2(uT[ii * PADA + r0 + m]);
                fma2(acc[m][0], uu, qa[m][0]);
                fma2(acc[m][1], uu, qa[m][1]);
            }
        } else {
            const float* S = (s == 0) ? uT : vT;   // linear u- then v-features
            #pragma unroll
            for (int kk = 0; kk < 32; ++kk) {
                float4 va = *(const float4*)&S[kk * PADA + r0];
                float4 vb = *(const float4*)&S[kk * PADA + r0 + 4];
                ulonglong2 Bv = *(const ulonglong2*)&Bc[(kk << 5) + c0];
                float vv[8] = {va.x, va.y, va.z, va.w, vb.x, vb.y, vb.z, vb.w};
                #pragma unroll
                for (int m = 0; m < 8; ++m) {
                    ull pp = pk2(vv[m]);
                    fma2(acc[m][0], pp, Bv.x);
                    fma2(acc[m][1], pp, Bv.y);
                }
            }
        }
    }

    float4 bav = *(const float4*)&ba[c0];
    int hoff = leftside ? 0 : 32;
    #pragma unroll
    for (int m = 0; m < 8; ++m) {
        float2 p0 = up2(acc[m][0]);
        float2 p1 = up2(acc[m][1]);
        float4 o;
        o.x = p0.x + bav.x; o.y = p0.y + bav.y;
        o.z = p1.x + bav.z; o.w = p1.y + bav.w;
        *(float4*)&g_lr[(size_t)(n0 + r0 + m) * 64 + hoff + c0] = o;
    }
}

// =====================================================================
// Kernel B: s = im(left,right) @ Ws1 + bs1; out = elu(s) @ Ws2 + bs2
// Grid: N/64 blocks x 256 threads. BM=64, BN=128, K=1088 factored.
// Dynamic smem: Bs ring 3x16KB + Lp + RT2 = 74496 B.
// =====================================================================
#define PADL 33
#define PADR 132
#define KM_SMEM_BYTES ((3 * 4096 + 64 * PADL + 32 * PADR) * 4)
__global__ __launch_bounds__(256, 2) void k_main(
    const float* __restrict__ Ws1, const float* __restrict__ bs1,
    const float* __restrict__ Ws2, const float* __restrict__ bs2,
    float* __restrict__ out)
{
    extern __shared__ __align__(16) float sm[];
    float* Bs  = sm;                       // [3][32*128]
    float* Lp  = sm + 3 * 4096;            // [64][PADL]
    float* RT2 = Lp + 64 * PADL;           // [32][PADR], duplicated pairs

    int tid = threadIdx.x;
    int n0 = blockIdx.x << 6;

    uint32_t bs_base = s2u(Bs);
    // prefetch chunks 0,1 : chunk s is a flat 16KB copy of Ws1[s*4096 ..]
    #pragma unroll
    for (int p = 0; p < 2; ++p) {
        #pragma unroll
        for (int q = 0; q < 4; ++q) {
            int e4 = q * 256 + tid;
            cpa16(bs_base + ((p % 3) * 4096 + e4 * 4) * 4,
                  Ws1 + (size_t)p * 4096 + e4 * 4);
        }
        cpa_commit();
    }

    #pragma unroll
    for (int it = 0; it < 16; ++it) {
        int e = it * 256 + tid;
        int r = e >> 6, k = e & 63;
        float v = g_lr[(size_t)(n0 + r) * 64 + k];
        if (k < 32) Lp[r * PADL + k] = v;
        else        *(ull*)&RT2[(k - 32) * PADR + (r << 1)] = pk2(v);
    }
    __syncthreads();

    int tc = tid & 31, w = tid >> 5;
    int c0 = tc << 2, r0 = w << 3;
    ull acc[8][2];
    #pragma unroll
    for (int m = 0; m < 8; ++m) { acc[m][0] = 0ull; acc[m][1] = 0ull; }

    for (int s = 0; s < 34; ++s) {
        cpa_wait<1>();
        __syncthreads();
        if (s + 2 < 34) {
            #pragma unroll
            for (int q = 0; q < 4; ++q) {
                int e4 = q * 256 + tid;
                cpa16(bs_base + (((s + 2) % 3) * 4096 + e4 * 4) * 4,
                      Ws1 + (size_t)(s + 2) * 4096 + e4 * 4);
            }
        }
        cpa_commit();

        const float* Bc = Bs + (s % 3) * 4096;

        if (s >= 2) {
            int ii = s - 2;
            ull qa[8][2];
            {   // kk = 0
                ulonglong2 Bv = *(const ulonglong2*)&Bc[c0];
                #pragma unroll
                for (int m = 0; m < 8; ++m) {
                    ull rv = *(const ull*)&RT2[(r0 + m) << 1];
                    qa[m][0] = mul2(rv, Bv.x);
                    qa[m][1] = mul2(rv, Bv.y);
                }
            }
            #pragma unroll
            for (int kk = 1; kk < 32; ++kk) {
                ulonglong2 Bv = *(const ulonglong2*)&Bc[(kk << 7) + c0];
                #pragma unroll
                for (int m = 0; m < 8; ++m) {
                    ull rv = *(const ull*)&RT2[kk * PADR + ((r0 + m) << 1)];
                    fma2(qa[m][0], rv, Bv.x);
                    fma2(qa[m][1], rv, Bv.y);
                }
            }
            #pragma unroll
            for (int m = 0; m < 8; ++m) {
                ull uu = pk2(Lp[(r0 + m) * PADL + ii]);
                fma2(acc[m][0], uu, qa[m][0]);
                fma2(acc[m][1], uu, qa[m][1]);
            }
        } else if (s == 0) {        // linear-left features
            #pragma unroll
            for (int kk = 0; kk < 32; ++kk) {
                ulonglong2 Bv = *(const ulonglong2*)&Bc[(kk << 7) + c0];
                #pragma unroll
                for (int m = 0; m < 8; ++m) {
                    ull pp = pk2(Lp[(r0 + m) * PADL + kk]);
                    fma2(acc[m][0], pp, Bv.x);
                    fma2(acc[m][1], pp, Bv.y);
                }
            }
        } else {                    // s == 1: linear-right features
            #pragma unroll
            for (int kk = 0; kk < 32; ++kk) {
                ulonglong2 Bv = *(const ulonglong2*)&Bc[(kk << 7) + c0];
                #pragma unroll
                for (int m = 0; m < 8; ++m) {
                    ull rv = *(const ull*)&RT2[kk * PADR + ((r0 + m) << 1)];
                    fma2(acc[m][0], rv, Bv.x);
                    fma2(acc[m][1], rv, Bv.y);
                }
            }
        }
    }

    // epilogue: +bs1, elu, dot with Ws2, warp-reduce over 128 cols
    float4 b1 = *(const float4*)&bs1[c0];
    float4 w2 = *(const float4*)&Ws2[c0];
    float bias2 = bs2[0];
    #pragma unroll
    for (int m = 0; m < 8; ++m) {
        float2 p0 = up2(acc[m][0]);
        float2 p1 = up2(acc[m][1]);
        float x0 = p0.x + b1.x, x1 = p0.y + b1.y;
        float x2 = p1.x + b1.z, x3 = p1.y + b1.w;
        float h0 = x0 > 0.f ? x0 : expm1f(x0);
        float h1 = x1 > 0.f ? x1 : expm1f(x1);
        float h2 = x2 > 0.f ? x2 : expm1f(x2);
        float h3 = x3 > 0.f ? x3 : expm1f(x3);
        float p = fmaf(h0, w2.x, fmaf(h1, w2.y, fmaf(h2, w2.z, h3 * w2.w)));
        #pragma unroll
        for (int off = 16; off; off >>= 1)
            p += __shfl_xor_sync(0xffffffffu, p, off);
        if (tc == 0) out[n0 + r0 + m] = p + bias2;
    }
}

extern "C" void kernel_launch(void* const* d_in, const int* in_sizes, int n_in,
                              void* d_out, int out_size)
{
    const float* concepts = (const float*)d_in[0];
    const float* Wn  = (const float*)d_in[1];
    const float* bn  = (const float*)d_in[2];
    const float* Wa  = (const float*)d_in[3];
    const float* ba  = (const float*)d_in[4];
    const float* Ws1 = (const float*)d_in[5];
    const float* bs1 = (const float*)d_in[6];
    const float* Ws2 = (const float*)d_in[7];
    const float* bs2 = (const float*)d_in[8];
    const void*  idx = d_in[9];
    int nrows = in_sizes[9] / 4;   // idx element count is N*4 for either dtype

    static int smem_set = 0;
    if (!smem_set) {
        cudaFuncSetAttribute(k_main, cudaFuncAttributeMaxDynamicSharedMemorySize,
                             KM_SMEM_BYTES);
        smem_set = 1;
    }

    k_lr<<<(nrows / 128) * 2, 128>>>(concepts, Wn, bn, Wa, ba, idx, nrows);
    k_main<<<nrows / 64, 256, KM_SMEM_BYTES>>>(Ws1, bs1, Ws2, bs2, (float*)d_out);
}

// round 5
// speedup vs baseline: 1.2754x; 1.2222x over previous
#include <cuda_runtime.h>
#include <cstdint>

#define NROWS_MAX 65536
typedef unsigned long long ull;

// 16 MB scratch: [n][0..31]=left, [n][32..63]=right
__device__ __align__(16) float g_lr[(size_t)NROWS_MAX * 64];

// ---------- packed f32x2 helpers ----------
__device__ __forceinline__ ull pk2(float x) {
    ull r; asm("mov.b64 %0, {%1, %1};" : "=l"(r) : "f"(x)); return r;
}
__device__ __forceinline__ void fma2(ull &d, ull a, ull b) {
    asm("fma.rn.f32x2 %0, %1, %2, %0;" : "+l"(d) : "l"(a), "l"(b));
}
__device__ __forceinline__ ull mul2(ull a, ull b) {
    ull d; asm("mul.rn.f32x2 %0, %1, %2;" : "=l"(d) : "l"(a), "l"(b)); return d;
}
__device__ __forceinline__ float2 up2(ull v) {
    float2 f; asm("mov.b64 {%0, %1}, %2;" : "=f"(f.x), "=f"(f.y) : "l"(v)); return f;
}
// ---------- cp.async helpers ----------
__device__ __forceinline__ uint32_t s2u(const void* p) {
    uint32_t a;
    asm("{ .reg .u64 t; cvta.to.shared.u64 t, %1; cvt.u32.u64 %0, t; }" : "=r"(a) : "l"(p));
    return a;
}
__device__ __forceinline__ void cpa16(uint32_t dst, const float* src) {
    asm volatile("cp.async.ca.shared.global [%0], [%1], 16;" :: "r"(dst), "l"(src));
}
__device__ __forceinline__ void cpa_commit() {
    asm volatile("cp.async.commit_group;");
}
template<int N> __device__ __forceinline__ void cpa_wait() {
    asm volatile("cp.async.wait_group %0;" :: "n"(N));
}

// =====================================================================
// Kernel A: left = im(na, b) @ Wa + ba ; right = im(c, d) @ Wa + ba
// Grid: 2*(N/128) blocks x 128 threads. BM=128, BN=32, K=1088 factored.
// M-packed f32x2: acc[p][c] holds rows (r0+2p, r0+2p+1) of column c0+c.
// =====================================================================
#define PADA 132
__global__ __launch_bounds__(128, 4) void k_lr(
    const float* __restrict__ concepts, const float* __restrict__ Wn,
    const float* __restrict__ bn, const float* __restrict__ Wa,
    const float* __restrict__ ba, const void* __restrict__ idxp,
    int nrows)
{
    __shared__ __align__(16) float uT[32 * PADA];   // uT[i][r]
    __shared__ __align__(16) float vT[32 * PADA];   // vT[j][r]
    __shared__ __align__(16) float Bs[3 * 1024];    // 3-stage ring of Wa chunks

    int tid  = threadIdx.x;
    int lane = tid & 31, w = tid >> 5;
    int nb128 = nrows >> 7;
    bool leftside = (blockIdx.x < (unsigned)nb128);
    int n0 = (leftside ? blockIdx.x : blockIdx.x - nb128) << 7;
    int cu_col = leftside ? 0 : 2;

    uint32_t bs_base = s2u(Bs);
    int e0 = tid * 2;                 // 2 x float4 per thread per 4KB chunk
    #pragma unroll
    for (int p = 0; p < 2; ++p) {
        #pragma unroll
        for (int q = 0; q < 2; ++q)
            cpa16(bs_base + ((p % 3) * 1024 + (e0 + q) * 4) * 4,
                  Wa + (size_t)p * 1024 + (e0 + q) * 4);
        cpa_commit();
    }

    // runtime int64-vs-int32 idx detection (int64 high words are all 0)
    const int* idx32 = (const int*)idxp;
    bool is64 = (idx32[1] == 0) & (idx32[3] == 0) & (idx32[5] == 0) & (idx32[7] == 0);
    const long long* idx64 = (const long long*)idxp;

    for (int it = 0; it < 32; ++it) {
        int r = it * 4 + w;
        long long base = (long long)(n0 + r) * 4 + cu_col;
        long long cu = is64 ? idx64[base]     : (long long)idx32[base];
        long long cv = is64 ? idx64[base + 1] : (long long)idx32[base + 1];
        uT[lane * PADA + r] = concepts[cu * 32 + lane];
        vT[lane * PADA + r] = concepts[cv * 32 + lane];
    }
    __syncthreads();

    if (leftside) {
        // na = a @ Wn + bn, in place over uT; Wn cached in registers
        float wn[32];
        #pragma unroll
        for (int i2 = 0; i2 < 32; ++i2) wn[i2] = Wn[i2 * 32 + lane];
        float bnk = bn[lane];
        for (int rr = 0; rr < 32; ++rr) {
            int r = (w << 5) + rr;
            float na = bnk;
            #pragma unroll
            for (int i2 = 0; i2 < 32; ++i2)
                na = fmaf(uT[i2 * PADA + r], wn[i2], na);
            __syncwarp();
            uT[lane * PADA + r] = na;
            __syncwarp();
        }
    }
    __syncthreads();

    // register tile: 8 rows (4 pairs) x 4 cols per thread
    int tc = tid & 7, tr = tid >> 3;
    int c0 = tc << 2, r0 = tr << 3;
    ull acc[4][4];
    #pragma unroll
    for (int p = 0; p < 4; ++p)
        #pragma unroll
        for (int c = 0; c < 4; ++c) acc[p][c] = 0ull;

    for (int s = 0; s < 34; ++s) {
        cpa_wait<1>();
        __syncthreads();
        if (s + 2 < 34) {
            #pragma unroll
            for (int q = 0; q < 2; ++q)
                cpa16(bs_base + (((s + 2) % 3) * 1024 + (e0 + q) * 4) * 4,
                      Wa + (size_t)(s + 2) * 1024 + (e0 + q) * 4);
        }
        cpa_commit();

        const float* Bc = Bs + (s % 3) * 1024;

        if (s >= 2) {
            int ii = s - 2;
            ull qa[4][4];
            #pragma unroll
            for (int kk = 0; kk < 32; ++kk) {
                float4 ra = *(const float4*)&vT[kk * PADA + r0];
                float4 rb = *(const float4*)&vT[kk * PADA + r0 + 4];
                ull rp[4] = { ((const ull*)&ra)[0], ((const ull*)&ra)[1],
                              ((const ull*)&rb)[0], ((const ull*)&rb)[1] };
                float4 bv = *(const float4*)&Bc[(kk << 5) + c0];
                ull bd[4] = { pk2(bv.x), pk2(bv.y), pk2(bv.z), pk2(bv.w) };
                if (kk == 0) {
                    #pragma unroll
                    for (int p = 0; p < 4; ++p)
                        #pragma unroll
                        for (int c = 0; c < 4; ++c)
                            qa[p][c] = mul2(rp[p], bd[c]);
                } else {
                    #pragma unroll
                    for (int p = 0; p < 4; ++p)
                        #pragma unroll
                        for (int c = 0; c < 4; ++c)
                            fma2(qa[p][c], rp[p], bd[c]);
                }
            }
            float4 ua = *(const float4*)&uT[ii * PADA + r0];
            float4 ub = *(const float4*)&uT[ii * PADA + r0 + 4];
            ull up[4] = { ((const ull*)&ua)[0], ((const ull*)&ua)[1],
                          ((const ull*)&ub)[0], ((const ull*)&ub)[1] };
            #pragma unroll
            for (int p = 0; p < 4; ++p)
                #pragma unroll
                for (int c = 0; c < 4; ++c)
                    fma2(acc[p][c], up[p], qa[p][c]);
        } else {
            const float* S = (s == 0) ? uT : vT;   // linear u- then v-features
            #pragma unroll
            for (int kk = 0; kk < 32; ++kk) {
                float4 ra = *(const float4*)&S[kk * PADA + r0];
                float4 rb = *(const float4*)&S[kk * PADA + r0 + 4];
                ull rp[4] = { ((const ull*)&ra)[0], ((const ull*)&ra)[1],
                              ((const ull*)&rb)[0], ((const ull*)&rb)[1] };
                float4 bv = *(const float4*)&Bc[(kk << 5) + c0];
                ull bd[4] = { pk2(bv.x), pk2(bv.y), pk2(bv.z), pk2(bv.w) };
                #pragma unroll
                for (int p = 0; p < 4; ++p)
                    #pragma unroll
                    for (int c = 0; c < 4; ++c)
                        fma2(acc[p][c], rp[p], bd[c]);
            }
        }
    }

    float4 bav = *(const float4*)&ba[c0];
    int hoff = leftside ? 0 : 32;
    #pragma unroll
    for (int p = 0; p < 4; ++p) {
        float2 v0 = up2(acc[p][0]);
        float2 v1 = up2(acc[p][1]);
        float2 v2 = up2(acc[p][2]);
        float2 v3 = up2(acc[p][3]);
        float4 oA = { v0.x + bav.x, v1.x + bav.y, v2.x + bav.z, v3.x + bav.w };
        float4 oB = { v0.y + bav.x, v1.y + bav.y, v2.y + bav.z, v3.y + bav.w };
        *(float4*)&g_lr[(size_t)(n0 + r0 + 2 * p)     * 64 + hoff + c0] = oA;
        *(float4*)&g_lr[(size_t)(n0 + r0 + 2 * p + 1) * 64 + hoff + c0] = oB;
    }
}

// =====================================================================
// Kernel B: s = im(left,right) @ Ws1 + bs1; out = elu(s) @ Ws2 + bs2
// Grid: N/64 blocks x 256 threads. BM=64, BN=128, K=1088 factored.
// M-packed f32x2. Dyn smem: Bs 3x16KB + LT + RT.
// =====================================================================
#define PADT 68
#define KM_SMEM_BYTES ((3 * 4096 + 2 * 32 * PADT) * 4)
__global__ __launch_bounds__(256, 2) void k_main(
    const float* __restrict__ Ws1, const float* __restrict__ bs1,
    const float* __restrict__ Ws2, const float* __restrict__ bs2,
    float* __restrict__ out)
{
    extern __shared__ __align__(16) float sm[];
    float* Bs = sm;                    // [3][32*128]
    float* LT = sm + 3 * 4096;         // LT[i][r], i<32, r<64
    float* RT = LT + 32 * PADT;        // RT[j][r]

    int tid = threadIdx.x;
    int n0 = blockIdx.x << 6;

    uint32_t bs_base = s2u(Bs);
    #pragma unroll
    for (int p = 0; p < 2; ++p) {
        #pragma unroll
        for (int q = 0; q < 4; ++q) {
            int e4 = q * 256 + tid;
            cpa16(bs_base + ((p % 3) * 4096 + e4 * 4) * 4,
                  Ws1 + (size_t)p * 4096 + e4 * 4);
        }
        cpa_commit();
    }

    #pragma unroll
    for (int it = 0; it < 16; ++it) {
        int e = it * 256 + tid;
        int r = e >> 6, k = e & 63;
        float v = g_lr[(size_t)(n0 + r) * 64 + k];
        if (k < 32) LT[k * PADT + r] = v;
        else        RT[(k - 32) * PADT + r] = v;
    }
    __syncthreads();

    int tc = tid & 31, w = tid >> 5;
    int c0 = tc << 2, r0 = w << 3;
    ull acc[4][4];
    #pragma unroll
    for (int p = 0; p < 4; ++p)
        #pragma unroll
        for (int c = 0; c < 4; ++c) acc[p][c] = 0ull;

    for (int s = 0; s < 34; ++s) {
        cpa_wait<1>();
        __syncthreads();
        if (s + 2 < 34) {
            #pragma unroll
            for (int q = 0; q < 4; ++q) {
                int e4 = q * 256 + tid;
                cpa16(bs_base + (((s + 2) % 3) * 4096 + e4 * 4) * 4,
                      Ws1 + (size_t)(s + 2) * 4096 + e4 * 4);
            }
        }
        cpa_commit();

        const float* Bc = Bs + (s % 3) * 4096;

        if (s >= 2) {
            int ii = s - 2;
            ull qa[4][4];
            #pragma unroll
            for (int kk = 0; kk < 32; ++kk) {
                float4 ra = *(const float4*)&RT[kk * PADT + r0];
                float4 rb = *(const float4*)&RT[kk * PADT + r0 + 4];
                ull rp[4] = { ((const ull*)&ra)[0], ((const ull*)&ra)[1],
                              ((const ull*)&rb)[0], ((const ull*)&rb)[1] };
                float4 bv = *(const float4*)&Bc[(kk << 7) + c0];
                ull bd[4] = { pk2(bv.x), pk2(bv.y), pk2(bv.z), pk2(bv.w) };
                if (kk == 0) {
                    #pragma unroll
                    for (int p = 0; p < 4; ++p)
                        #pragma unroll
                        for (int c = 0; c < 4; ++c)
                            qa[p][c] = mul2(rp[p], bd[c]);
                } else {
                    #pragma unroll
                    for (int p = 0; p < 4; ++p)
                        #pragma unroll
                        for (int c = 0; c < 4; ++c)
                            fma2(qa[p][c], rp[p], bd[c]);
                }
            }
            float4 ua = *(const float4*)&LT[ii * PADT + r0];
            float4 ub = *(const float4*)&LT[ii * PADT + r0 + 4];
            ull up[4] = { ((const ull*)&ua)[0], ((const ull*)&ua)[1],
                          ((const ull*)&ub)[0], ((const ull*)&ub)[1] };
            #pragma unroll
            for (int p = 0; p < 4; ++p)
                #pragma unroll
                for (int c = 0; c < 4; ++c)
                    fma2(acc[p][c], up[p], qa[p][c]);
        } else {
            const float* S = (s == 0) ? LT : RT;   // linear left/right features
            #pragma unroll
            for (int kk = 0; kk < 32; ++kk) {
                float4 ra = *(const float4*)&S[kk * PADT + r0];
                float4 rb = *(const float4*)&S[kk * PADT + r0 + 4];
                ull rp[4] = { ((const ull*)&ra)[0], ((const ull*)&ra)[1],
                              ((const ull*)&rb)[0], ((const ull*)&rb)[1] };
                float4 bv = *(const float4*)&Bc[(kk << 7) + c0];
                ull bd[4] = { pk2(bv.x), pk2(bv.y), pk2(bv.z), pk2(bv.w) };
                #pragma unroll
                for (int p = 0; p < 4; ++p)
                    #pragma unroll
                    for (int c = 0; c < 4; ++c)
                        fma2(acc[p][c], rp[p], bd[c]);
            }
        }
    }

    // epilogue: +bs1, elu, dot with Ws2, warp-reduce over 128 cols
    float4 b1 = *(const float4*)&bs1[c0];
    float4 w2 = *(const float4*)&Ws2[c0];
    float bias2 = bs2[0];
    #pragma unroll
    for (int p = 0; p < 4; ++p) {
        float2 v0 = up2(acc[p][0]);
        float2 v1 = up2(acc[p][1]);
        float2 v2 = up2(acc[p][2]);
        float2 v3 = up2(acc[p][3]);
        float rows[2][4] = { { v0.x, v1.x, v2.x, v3.x },
                             { v0.y, v1.y, v2.y, v3.y } };
        #pragma unroll
        for (int h = 0; h < 2; ++h) {
            float x0 = rows[h][0] + b1.x, x1 = rows[h][1] + b1.y;
            float x2 = rows[h][2] + b1.z, x3 = rows[h][3] + b1.w;
            float h0 = x0 > 0.f ? x0 : expm1f(x0);
            float h1 = x1 > 0.f ? x1 : expm1f(x1);
            float h2 = x2 > 0.f ? x2 : expm1f(x2);
            float h3 = x3 > 0.f ? x3 : expm1f(x3);
            float pd = fmaf(h0, w2.x, fmaf(h1, w2.y, fmaf(h2, w2.z, h3 * w2.w)));
            #pragma unroll
            for (int off = 16; off; off >>= 1)
                pd += __shfl_xor_sync(0xffffffffu, pd, off);
            if (tc == 0) out[n0 + r0 + 2 * p + h] = pd + bias2;
        }
    }
}

extern "C" void kernel_launch(void* const* d_in, const int* in_sizes, int n_in,
                              void* d_out, int out_size)
{
    const float* concepts = (const float*)d_in[0];
    const float* Wn  = (const float*)d_in[1];
    const float* bn  = (const float*)d_in[2];
    const float* Wa  = (const float*)d_in[3];
    const float* ba  = (const float*)d_in[4];
    const float* Ws1 = (const float*)d_in[5];
    const float* bs1 = (const float*)d_in[6];
    const float* Ws2 = (const float*)d_in[7];
    const float* bs2 = (const float*)d_in[8];
    const void*  idx = d_in[9];
    int nrows = in_sizes[9] / 4;

    static int smem_set = 0;
    if (!smem_set) {
        cudaFuncSetAttribute(k_main, cudaFuncAttributeMaxDynamicSharedMemorySize,
                             KM_SMEM_BYTES);
        smem_set = 1;
    }

    k_lr<<<(nrows / 128) * 2, 128>>>(concepts, Wn, bn, Wa, ba, idx, nrows);
    k_main<<<nrows / 64, 256, KM_SMEM_BYTES>>>(Ws1, bs1, Ws2, bs2, (float*)d_out);
}